// round 12
// baseline (speedup 1.0000x reference)
#include <cuda_runtime.h>
#include <cuda_bf16.h>
#include <cstdint>

#define NN 8192
#define FOUT 256

// smem layout (bytes, dynamic) — M=64 x N=64 tiles, 128-thread CTAs
#define PH_OFF 0u
#define PH_SZ  5120u             // 64 rows x 80B
#define PL_OFF 10240u
#define WH_OFF 20480u
#define WH_SZ  9216u             // 64 n x 144B
#define ZS_OFF 38912u
#define SM_TOT 39168u

// ---------------- scratch globals ----------------
__device__ float g_Wh[NN * FOUT];                                  // 8 MB
__device__ __align__(16) __nv_bfloat16 g_WhTi[256 * 256 * 64];     // [jtile][n][hi32|lo32]
__device__ float g_E1[NN], g_B1[NN], g_E2[NN], g_F2[NN];

__device__ __forceinline__ uint32_t s2u(const void* p) {
    uint32_t a;
    asm("{ .reg .u64 t; cvta.to.shared.u64 t, %1; cvt.u32.u64 %0, t; }" : "=r"(a) : "l"(p));
    return a;
}
__device__ __forceinline__ void mma16816(float* d, const uint32_t* a,
                                         uint32_t b0, uint32_t b1) {
    asm volatile(
        "mma.sync.aligned.m16n8k16.row.col.f32.bf16.bf16.f32 "
        "{%0,%1,%2,%3}, {%4,%5,%6,%7}, {%8,%9}, {%0,%1,%2,%3};"
        : "+f"(d[0]), "+f"(d[1]), "+f"(d[2]), "+f"(d[3])
        : "r"(a[0]), "r"(a[1]), "r"(a[2]), "r"(a[3]), "r"(b0), "r"(b1));
}
__device__ __forceinline__ void ldsm4(uint32_t* r, uint32_t addr) {
    asm volatile("ldmatrix.sync.aligned.m8n8.x4.shared.b16 {%0,%1,%2,%3}, [%4];"
                 : "=r"(r[0]), "=r"(r[1]), "=r"(r[2]), "=r"(r[3]) : "r"(addr));
}

// ---------------------------------------------------------------------------
// K1: Wh = h @ W   (512 blocks x 256 thr, 16 rows/block)
// ---------------------------------------------------------------------------
__global__ void __launch_bounds__(256) k_wh(const float* __restrict__ h,
                                            const float* __restrict__ W) {
    __shared__ float Ws[32][256];
    __shared__ float hs[16][32];
    int t = threadIdx.x, r0 = blockIdx.x * 16;
    float acc[16];
#pragma unroll
    for (int r = 0; r < 16; r++) acc[r] = 0.f;
    for (int kc = 0; kc < 8; kc++) {
        __syncthreads();
#pragma unroll
        for (int kk = 0; kk < 32; kk++) Ws[kk][t] = W[(kc * 32 + kk) * FOUT + t];
        {
            int r = t >> 4, c2 = (t & 15) * 2;
            float2 v = *(const float2*)&h[(r0 + r) * FOUT + kc * 32 + c2];
            hs[r][c2] = v.x; hs[r][c2 + 1] = v.y;
        }
        __syncthreads();
#pragma unroll
        for (int kk = 0; kk < 32; kk++) {
            float w = Ws[kk][t];
#pragma unroll
            for (int r = 0; r < 16; r++) acc[r] = fmaf(hs[r][kk], w, acc[r]);
        }
    }
#pragma unroll
    for (int r = 0; r < 16; r++) g_Wh[(r0 + r) * FOUT + t] = acc[r];
}

// ---------------------------------------------------------------------------
// K1t: WhTi[kb][n][64] = [hi bf16 of Wh[kb*32+r][n] r=0..31 | lo ...]
// ---------------------------------------------------------------------------
__global__ void __launch_bounds__(256) k_tr() {
    int t = threadIdx.x, kb = blockIdx.x;
    float v[32];
#pragma unroll
    for (int r = 0; r < 32; r++) v[r] = g_Wh[(kb * 32 + r) * FOUT + t];
    uint32_t hi16[16], lo16[16];
#pragma unroll
    for (int rp = 0; rp < 16; rp++) {
        float v0 = v[2 * rp], v1 = v[2 * rp + 1];
        __nv_bfloat16 h0 = __float2bfloat16(v0), h1 = __float2bfloat16(v1);
        float l0 = v0 - __bfloat162float(h0), l1 = v1 - __bfloat162float(h1);
        __nv_bfloat16 g0 = __float2bfloat16(l0), g1 = __float2bfloat16(l1);
        hi16[rp] = (uint32_t)__bfloat16_as_ushort(h1) << 16 | __bfloat16_as_ushort(h0);
        lo16[rp] = (uint32_t)__bfloat16_as_ushort(g1) << 16 | __bfloat16_as_ushort(g0);
    }
    __nv_bfloat16* dst = &g_WhTi[((size_t)kb * 256 + t) * 64];
#pragma unroll
    for (int s = 0; s < 4; s++) {
        *(uint4*)(dst + s * 8)      = make_uint4(hi16[4*s], hi16[4*s+1], hi16[4*s+2], hi16[4*s+3]);
        *(uint4*)(dst + 32 + s * 8) = make_uint4(lo16[4*s], lo16[4*s+1], lo16[4*s+2], lo16[4*s+3]);
    }
}

// ---------------------------------------------------------------------------
// K1b: s1,s2 -> exp factors. exp(lrelu(s1+s2)) = max(E1*E2, B1*F2).
// ---------------------------------------------------------------------------
__global__ void __launch_bounds__(256) k_s12(const float* __restrict__ a) {
    int warp = threadIdx.x >> 5, lane = threadIdx.x & 31;
    int r = blockIdx.x * 8 + warp;
    const float4* wh = (const float4*)&g_Wh[r * FOUT];
    float v1 = 0.f, v2 = 0.f;
#pragma unroll
    for (int i = 0; i < 2; i++) {
        int k4 = lane + i * 32;
        float4 w  = wh[k4];
        float4 a1 = *(const float4*)&a[k4 * 4];
        float4 a2 = *(const float4*)&a[FOUT + k4 * 4];
        v1 += w.x * a1.x + w.y * a1.y + w.z * a1.z + w.w * a1.w;
        v2 += w.x * a2.x + w.y * a2.y + w.z * a2.z + w.w * a2.w;
    }
#pragma unroll
    for (int o = 16; o; o >>= 1) {
        v1 += __shfl_down_sync(~0u, v1, o);
        v2 += __shfl_down_sync(~0u, v2, o);
    }
    if (lane == 0) {
        g_E1[r] = __expf(v1);  g_B1[r] = __expf(0.2f * v1);
        g_E2[r] = __expf(v2);  g_F2[r] = __expf(0.2f * v2);
    }
}

// ---------------------------------------------------------------------------
// K2: fused P-gen + HMMA, pipelined; 128-thread CTAs, 4 CTAs/SM.
// 512 CTAs = 128 row-blocks (M=64) x 4 col-blocks (N=64).
// 4 warps, warp tile 16m x 64n -> acc 8nt x 4 = 32 regs.
// ---------------------------------------------------------------------------
__global__ void __launch_bounds__(128, 4) k_attn(const int* __restrict__ adj,
                                                 float* __restrict__ out) {
    extern __shared__ char sm[];
    uint32_t sb = s2u(sm);

    int t = threadIdx.x;
    int rb = blockIdx.x >> 2, cb = blockIdx.x & 3;
    int r0 = rb * 64;
    int w = t >> 5, lane = t & 31;
    int kp = t & 15, rsub = t >> 4;       // rsub 0..7
    int g = lane >> 2, quad = lane & 3;
    int mb = w * 16;                      // warp m base: 0,16,32,48

    // ldmatrix base addresses (buf 0)
    uint32_t aAddr = sb + PH_OFF + (uint32_t)((mb + (lane & 15)) * 80 + (lane >> 4) * 16);
    uint32_t bAddr = sb + WH_OFF +
        (uint32_t)(((lane >> 4) * 8 + (lane & 7)) * 144 + ((lane >> 3) & 1) * 16);

    // cp.async: 64 n rows x 128B / 128 thr = 64B each
    int cn = t >> 1, chalf = t & 1;
    uint32_t cpDst = sb + WH_OFF + (uint32_t)(cn * 144 + chalf * 64);
    const char* cpSrcBase =
        (const char*)&g_WhTi[((size_t)cb * 64 + cn) * 64 + chalf * 32];

    float e1r[8], b1r[8], zacc[8];
#pragma unroll
    for (int it = 0; it < 8; it++) {
        int r = it * 8 + rsub;
        e1r[it] = g_E1[r0 + r];
        b1r[it] = g_B1[r0 + r];
        zacc[it] = 0.f;
    }

    float acc[8][4];
#pragma unroll
    for (int nt = 0; nt < 8; nt++)
#pragma unroll
        for (int e = 0; e < 4; e++) acc[nt][e] = 0.f;

    int2 adjv[8];
#pragma unroll
    for (int it = 0; it < 8; it++)
        adjv[it] = *(const int2*)&adj[(long long)(r0 + it * 8 + rsub) * NN + 2 * kp];

    auto gen = [&](int ti, uint32_t buf) {
        char* phb = sm + PH_OFF + buf * PH_SZ;
        char* plb = sm + PL_OFF + buf * PH_SZ;
        float2 e2 = *(const float2*)&g_E2[ti * 32 + 2 * kp];
        float2 f2 = *(const float2*)&g_F2[ti * 32 + 2 * kp];
#pragma unroll
        for (int it = 0; it < 8; it++) {
            int r = it * 8 + rsub;
            float p0 = adjv[it].x ? fmaxf(e1r[it] * e2.x, b1r[it] * f2.x) : 0.f;
            float p1 = adjv[it].y ? fmaxf(e1r[it] * e2.y, b1r[it] * f2.y) : 0.f;
            zacc[it] += p0 + p1;
            uint32_t hp;
            asm("cvt.rn.bf16x2.f32 %0, %1, %2;" : "=r"(hp) : "f"(p1), "f"(p0));
            float h0f = __uint_as_float(hp << 16);
            float h1f = __uint_as_float(hp & 0xffff0000u);
            uint32_t lp;
            asm("cvt.rn.bf16x2.f32 %0, %1, %2;" : "=r"(lp) : "f"(p1 - h1f), "f"(p0 - h0f));
            *(uint32_t*)(phb + r * 80 + kp * 4) = hp;
            *(uint32_t*)(plb + r * 80 + kp * 4) = lp;
        }
    };
    auto cpWh = [&](int ti, uint32_t buf) {
        const char* src = cpSrcBase + (size_t)ti * 32768;   // 256 n x 64 bf16 x 2B per tile
        uint32_t d = cpDst + buf * WH_SZ;
#pragma unroll
        for (int s4 = 0; s4 < 4; s4++)
            asm volatile("cp.async.cg.shared.global [%0], [%1], 16;"
                         :: "r"(d + s4 * 16), "l"(src + s4 * 16) : "memory");
        asm volatile("cp.async.commit_group;" ::: "memory");
    };

    // ---- prologue
    cpWh(0, 0);
    gen(0, 0);
#pragma unroll
    for (int it = 0; it < 8; it++)
        adjv[it] = *(const int2*)&adj[(long long)(r0 + it * 8 + rsub) * NN + 32 + 2 * kp];

    for (int i = 0; i < 256; i++) {
        uint32_t cur = i & 1, nxt = cur ^ 1;
        asm volatile("cp.async.wait_group 0;" ::: "memory");
        __syncthreads();

        if (i < 255) {
            cpWh(i + 1, nxt);
            gen(i + 1, nxt);
            if (i < 254) {
#pragma unroll
                for (int it = 0; it < 8; it++)
                    adjv[it] = *(const int2*)&adj[(long long)(r0 + it * 8 + rsub) * NN
                                                 + (i + 2) * 32 + 2 * kp];
            }
        }

        // ---- MMA(i)
        uint32_t aH = aAddr + cur * PH_SZ;
        uint32_t aL = aH + 10240u;            // PL_OFF - PH_OFF
        uint32_t bB = bAddr + cur * WH_SZ;
#pragma unroll
        for (int ks = 0; ks < 2; ks++) {
            uint32_t Ah[4], Al[4], Bh[4][4], Bl[4][4];
            ldsm4(Ah, aH + ks * 32);
            ldsm4(Al, aL + ks * 32);
#pragma unroll
            for (int np = 0; np < 4; np++) {
                ldsm4(Bh[np], bB + np * 2304 + ks * 32);
                ldsm4(Bl[np], bB + np * 2304 + ks * 32 + 64);
            }
#pragma unroll
            for (int np = 0; np < 4; np++) {
                mma16816(acc[2*np],   Ah, Bh[np][0], Bh[np][1]);
                mma16816(acc[2*np+1], Ah, Bh[np][2], Bh[np][3]);
            }
#pragma unroll
            for (int np = 0; np < 4; np++) {
                mma16816(acc[2*np],   Al, Bh[np][0], Bh[np][1]);
                mma16816(acc[2*np+1], Al, Bh[np][2], Bh[np][3]);
            }
#pragma unroll
            for (int np = 0; np < 4; np++) {
                mma16816(acc[2*np],   Ah, Bl[np][0], Bl[np][1]);
                mma16816(acc[2*np+1], Ah, Bl[np][2], Bl[np][3]);
            }
        }
    }

    // ---- Z reduce (16 kp lanes per row; rows it*8+rsub)
    float* Zs = (float*)(sm + ZS_OFF);
#pragma unroll
    for (int it = 0; it < 8; it++) {
        float z = zacc[it];
        z += __shfl_xor_sync(~0u, z, 1);
        z += __shfl_xor_sync(~0u, z, 2);
        z += __shfl_xor_sync(~0u, z, 4);
        z += __shfl_xor_sync(~0u, z, 8);
        if ((lane & 15) == 0) Zs[it * 8 + rsub] = z;
    }
    __syncthreads();

    // ---- epilogue
    {
        int rl = mb + g;
        float zi0 = __frcp_rn(Zs[rl]);
        float zi1 = __frcp_rn(Zs[rl + 8]);
#pragma unroll
        for (int nt = 0; nt < 8; nt++) {
            int c = cb * 64 + nt * 8 + quad * 2;
            *(float2*)&out[(size_t)(r0 + rl) * FOUT + c] =
                make_float2(acc[nt][0] * zi0, acc[nt][1] * zi0);
            *(float2*)&out[(size_t)(r0 + rl + 8) * FOUT + c] =
                make_float2(acc[nt][2] * zi1, acc[nt][3] * zi1);
        }
    }
}

// ---------------------------------------------------------------------------
extern "C" void kernel_launch(void* const* d_in, const int* in_sizes, int n_in,
                              void* d_out, int out_size) {
    const float* h   = (const float*)d_in[0];
    const int*   adj = (const int*)d_in[1];
    const float* W   = (const float*)d_in[2];
    const float* a   = (const float*)d_in[3];
    float* out = (float*)d_out;

    cudaFuncSetAttribute(k_attn, cudaFuncAttributeMaxDynamicSharedMemorySize, SM_TOT);

    k_wh<<<512, 256>>>(h, W);
    k_tr<<<256, 256>>>();
    k_s12<<<1024, 256>>>(a);
    k_attn<<<512, 128, SM_TOT>>>(adj, out);
}

// round 13
// speedup vs baseline: 1.1343x; 1.1343x over previous
#include <cuda_runtime.h>
#include <cuda_bf16.h>
#include <cstdint>

#define NN 8192
#define FOUT 256

// per-stage layout: PH(5120) PL(5120) WH(18432) = 28672 B, 3 stages
#define STG_SZ 28672u
#define PL_D   5120u
#define WH_D   10240u
#define MB_OFF 86016u            // 6 mbarriers (full/empty x3), 16B apart
#define ZS_OFF 86144u
#define SM_TOT 86400u

// ---------------- scratch globals ----------------
__device__ float g_Wh[NN * FOUT];                                  // 8 MB
__device__ __align__(16) __nv_bfloat16 g_WhTi[256 * 256 * 64];     // [jtile][n][hi32|lo32]
__device__ float g_E1[NN], g_B1[NN], g_E2[NN], g_F2[NN];

__device__ __forceinline__ uint32_t s2u(const void* p) {
    uint32_t a;
    asm("{ .reg .u64 t; cvta.to.shared.u64 t, %1; cvt.u32.u64 %0, t; }" : "=r"(a) : "l"(p));
    return a;
}
__device__ __forceinline__ void mma16816(float* d, const uint32_t* a,
                                         uint32_t b0, uint32_t b1) {
    asm volatile(
        "mma.sync.aligned.m16n8k16.row.col.f32.bf16.bf16.f32 "
        "{%0,%1,%2,%3}, {%4,%5,%6,%7}, {%8,%9}, {%0,%1,%2,%3};"
        : "+f"(d[0]), "+f"(d[1]), "+f"(d[2]), "+f"(d[3])
        : "r"(a[0]), "r"(a[1]), "r"(a[2]), "r"(a[3]), "r"(b0), "r"(b1));
}
__device__ __forceinline__ void ldsm4(uint32_t* r, uint32_t addr) {
    asm volatile("ldmatrix.sync.aligned.m8n8.x4.shared.b16 {%0,%1,%2,%3}, [%4];"
                 : "=r"(r[0]), "=r"(r[1]), "=r"(r[2]), "=r"(r[3]) : "r"(addr));
}
__device__ __forceinline__ void mbar_wait(uint32_t mb, uint32_t par) {
    asm volatile(
        "{\n\t.reg .pred P1;\n\tW%=:\n\t"
        "mbarrier.try_wait.parity.acquire.cta.shared::cta.b64 P1, [%0], %1, 0x989680;\n\t"
        "@P1 bra.uni D%=;\n\tbra.uni W%=;\n\tD%=:\n\t}"
        :: "r"(mb), "r"(par) : "memory");
}
__device__ __forceinline__ void mbar_arrive(uint32_t mb) {
    asm volatile("mbarrier.arrive.shared.b64 _, [%0];" :: "r"(mb) : "memory");
}

// ---------------------------------------------------------------------------
// K1: Wh = h @ W
// ---------------------------------------------------------------------------
__global__ void __launch_bounds__(256) k_wh(const float* __restrict__ h,
                                            const float* __restrict__ W) {
    __shared__ float Ws[32][256];
    __shared__ float hs[16][32];
    int t = threadIdx.x, r0 = blockIdx.x * 16;
    float acc[16];
#pragma unroll
    for (int r = 0; r < 16; r++) acc[r] = 0.f;
    for (int kc = 0; kc < 8; kc++) {
        __syncthreads();
#pragma unroll
        for (int kk = 0; kk < 32; kk++) Ws[kk][t] = W[(kc * 32 + kk) * FOUT + t];
        {
            int r = t >> 4, c2 = (t & 15) * 2;
            float2 v = *(const float2*)&h[(r0 + r) * FOUT + kc * 32 + c2];
            hs[r][c2] = v.x; hs[r][c2 + 1] = v.y;
        }
        __syncthreads();
#pragma unroll
        for (int kk = 0; kk < 32; kk++) {
            float w = Ws[kk][t];
#pragma unroll
            for (int r = 0; r < 16; r++) acc[r] = fmaf(hs[r][kk], w, acc[r]);
        }
    }
#pragma unroll
    for (int r = 0; r < 16; r++) g_Wh[(r0 + r) * FOUT + t] = acc[r];
}

// ---------------------------------------------------------------------------
// K1t: WhTi[kb][n][64] = [hi bf16 of Wh[kb*32+r][n] r=0..31 | lo ...]
// ---------------------------------------------------------------------------
__global__ void __launch_bounds__(256) k_tr() {
    int t = threadIdx.x, kb = blockIdx.x;
    float v[32];
#pragma unroll
    for (int r = 0; r < 32; r++) v[r] = g_Wh[(kb * 32 + r) * FOUT + t];
    uint32_t hi16[16], lo16[16];
#pragma unroll
    for (int rp = 0; rp < 16; rp++) {
        float v0 = v[2 * rp], v1 = v[2 * rp + 1];
        __nv_bfloat16 h0 = __float2bfloat16(v0), h1 = __float2bfloat16(v1);
        float l0 = v0 - __bfloat162float(h0), l1 = v1 - __bfloat162float(h1);
        __nv_bfloat16 g0 = __float2bfloat16(l0), g1 = __float2bfloat16(l1);
        hi16[rp] = (uint32_t)__bfloat16_as_ushort(h1) << 16 | __bfloat16_as_ushort(h0);
        lo16[rp] = (uint32_t)__bfloat16_as_ushort(g1) << 16 | __bfloat16_as_ushort(g0);
    }
    __nv_bfloat16* dst = &g_WhTi[((size_t)kb * 256 + t) * 64];
#pragma unroll
    for (int s = 0; s < 4; s++) {
        *(uint4*)(dst + s * 8)      = make_uint4(hi16[4*s], hi16[4*s+1], hi16[4*s+2], hi16[4*s+3]);
        *(uint4*)(dst + 32 + s * 8) = make_uint4(lo16[4*s], lo16[4*s+1], lo16[4*s+2], lo16[4*s+3]);
    }
}

// ---------------------------------------------------------------------------
// K1b: exp factors
// ---------------------------------------------------------------------------
__global__ void __launch_bounds__(256) k_s12(const float* __restrict__ a) {
    int warp = threadIdx.x >> 5, lane = threadIdx.x & 31;
    int r = blockIdx.x * 8 + warp;
    const float4* wh = (const float4*)&g_Wh[r * FOUT];
    float v1 = 0.f, v2 = 0.f;
#pragma unroll
    for (int i = 0; i < 2; i++) {
        int k4 = lane + i * 32;
        float4 w  = wh[k4];
        float4 a1 = *(const float4*)&a[k4 * 4];
        float4 a2 = *(const float4*)&a[FOUT + k4 * 4];
        v1 += w.x * a1.x + w.y * a1.y + w.z * a1.z + w.w * a1.w;
        v2 += w.x * a2.x + w.y * a2.y + w.z * a2.z + w.w * a2.w;
    }
#pragma unroll
    for (int o = 16; o; o >>= 1) {
        v1 += __shfl_down_sync(~0u, v1, o);
        v2 += __shfl_down_sync(~0u, v2, o);
    }
    if (lane == 0) {
        g_E1[r] = __expf(v1);  g_B1[r] = __expf(0.2f * v1);
        g_E2[r] = __expf(v2);  g_F2[r] = __expf(0.2f * v2);
    }
}

// ---------------------------------------------------------------------------
// K2: warp-specialized producer/consumer + HMMA.
// 256 CTAs = 128 rb (M=64) x 2 cb (N=128). 256 thr: warps 0-3 produce,
// warps 4-7 consume (warp tile M16 x N128). 3-stage mbarrier ring.
// ---------------------------------------------------------------------------
__global__ void __launch_bounds__(256, 2) k_attn(const int* __restrict__ adj,
                                                 float* __restrict__ out) {
    extern __shared__ char sm[];
    uint32_t sb = s2u(sm);
    uint32_t mbF = sb + MB_OFF;        // full[s] at +s*16, empty[s] at +s*16+8

    int t = threadIdx.x, w = t >> 5, lane = t & 31;
    int rb = blockIdx.x >> 1, cb = blockIdx.x & 1;
    int r0 = rb * 64;

    if (t == 0) {
#pragma unroll
        for (int s = 0; s < 3; s++) {
            asm volatile("mbarrier.init.shared.b64 [%0], 128;" :: "r"(mbF + s * 16) : "memory");
            asm volatile("mbarrier.init.shared.b64 [%0], 128;" :: "r"(mbF + s * 16 + 8) : "memory");
        }
    }
    __syncthreads();

    if (w < 4) {
        // ================= PRODUCER (128 threads) =================
        int kp = t & 15, rsub = t >> 4;          // rsub 0..7
        uint32_t whDst = sb + WH_D + (uint32_t)(t * 144);
        const char* cpSrc = (const char*)&g_WhTi[((size_t)cb * 128 + t) * 64];

        float e1r[8], b1r[8], zacc[8];
#pragma unroll
        for (int it = 0; it < 8; it++) {
            int r = it * 8 + rsub;
            e1r[it] = g_E1[r0 + r];
            b1r[it] = g_B1[r0 + r];
            zacc[it] = 0.f;
        }
        int2 adjv[8];
#pragma unroll
        for (int it = 0; it < 8; it++)
            adjv[it] = *(const int2*)&adj[(long long)(r0 + it * 8 + rsub) * NN + 2 * kp];

        int s = 0; uint32_t kpar = 0;
        for (int i = 0; i < 256; i++) {
            mbar_wait(mbF + s * 16 + 8, 1u ^ kpar);      // empty[s]
            uint32_t stg = s * STG_SZ;
            // Wh tile cp.async (128B/thread from pre-split WhTi)
            {
                const char* src = cpSrc + (size_t)i * 32768;
                uint32_t d = whDst + stg;
#pragma unroll
                for (int s4 = 0; s4 < 8; s4++)
                    asm volatile("cp.async.cg.shared.global [%0], [%1], 16;"
                                 :: "r"(d + s4 * 16), "l"(src + s4 * 16) : "memory");
                asm volatile("cp.async.commit_group;" ::: "memory");
            }
            // P gen into stage s
            {
                char* phb = sm + stg;
                char* plb = sm + stg + PL_D;
                float2 e2 = *(const float2*)&g_E2[i * 32 + 2 * kp];
                float2 f2 = *(const float2*)&g_F2[i * 32 + 2 * kp];
#pragma unroll
                for (int it = 0; it < 8; it++) {
                    int r = it * 8 + rsub;
                    float p0 = adjv[it].x ? fmaxf(e1r[it] * e2.x, b1r[it] * f2.x) : 0.f;
                    float p1 = adjv[it].y ? fmaxf(e1r[it] * e2.y, b1r[it] * f2.y) : 0.f;
                    zacc[it] += p0 + p1;
                    uint32_t hp;
                    asm("cvt.rn.bf16x2.f32 %0, %1, %2;" : "=r"(hp) : "f"(p1), "f"(p0));
                    float h0f = __uint_as_float(hp << 16);
                    float h1f = __uint_as_float(hp & 0xffff0000u);
                    uint32_t lp;
                    asm("cvt.rn.bf16x2.f32 %0, %1, %2;" : "=r"(lp) : "f"(p1 - h1f), "f"(p0 - h0f));
                    *(uint32_t*)(phb + r * 80 + kp * 4) = hp;
                    *(uint32_t*)(plb + r * 80 + kp * 4) = lp;
                }
            }
            // adj prefetch for next tile
            if (i < 255) {
#pragma unroll
                for (int it = 0; it < 8; it++)
                    adjv[it] = *(const int2*)&adj[(long long)(r0 + it * 8 + rsub) * NN
                                                 + (i + 1) * 32 + 2 * kp];
            }
            asm volatile("cp.async.wait_group 0;" ::: "memory");
            mbar_arrive(mbF + s * 16);                   // full[s]
            if (++s == 3) { s = 0; kpar ^= 1u; }
        }

        // Z reduce -> Zs
        float* Zs = (float*)(sm + ZS_OFF);
#pragma unroll
        for (int it = 0; it < 8; it++) {
            float z = zacc[it];
            z += __shfl_xor_sync(~0u, z, 1);
            z += __shfl_xor_sync(~0u, z, 2);
            z += __shfl_xor_sync(~0u, z, 4);
            z += __shfl_xor_sync(~0u, z, 8);
            if ((lane & 15) == 0) Zs[it * 8 + rsub] = z;
        }
    } else {
        // ================= CONSUMER (warps 4-7) =================
        int cw = w - 4;
        int mb = cw * 16;
        uint32_t aBase = sb + (uint32_t)((mb + (lane & 15)) * 80 + (lane >> 4) * 16);
        uint32_t bBase = sb + WH_D +
            (uint32_t)(((lane >> 4) * 8 + (lane & 7)) * 144 + ((lane >> 3) & 1) * 16);

        float acc[16][4];
#pragma unroll
        for (int nt = 0; nt < 16; nt++)
#pragma unroll
            for (int e = 0; e < 4; e++) acc[nt][e] = 0.f;

        int s = 0; uint32_t kpar = 0;
        for (int i = 0; i < 256; i++) {
            mbar_wait(mbF + s * 16, kpar);               // full[s]
            uint32_t stg = s * STG_SZ;
            uint32_t aH = aBase + stg, aL = aH + PL_D, bB = bBase + stg;
#pragma unroll
            for (int ks = 0; ks < 2; ks++) {
                uint32_t Ah[4], Al[4];
                ldsm4(Ah, aH + ks * 32);
                ldsm4(Al, aL + ks * 32);
#pragma unroll
                for (int npp = 0; npp < 4; npp++) {
                    uint32_t Bh0[4], Bh1[4], Bl0[4], Bl1[4];
                    uint32_t bb0 = bB + (2 * npp) * 2304 + ks * 32;
                    uint32_t bb1 = bb0 + 2304;
                    ldsm4(Bh0, bb0); ldsm4(Bh1, bb1);
                    ldsm4(Bl0, bb0 + 64); ldsm4(Bl1, bb1 + 64);
                    int a0 = 4 * npp;
                    mma16816(acc[a0],     Ah, Bh0[0], Bh0[1]);
                    mma16816(acc[a0 + 1], Ah, Bh0[2], Bh0[3]);
                    mma16816(acc[a0 + 2], Ah, Bh1[0], Bh1[1]);
                    mma16816(acc[a0 + 3], Ah, Bh1[2], Bh1[3]);
                    mma16816(acc[a0],     Al, Bh0[0], Bh0[1]);
                    mma16816(acc[a0 + 1], Al, Bh0[2], Bh0[3]);
                    mma16816(acc[a0 + 2], Al, Bh1[0], Bh1[1]);
                    mma16816(acc[a0 + 3], Al, Bh1[2], Bh1[3]);
                    mma16816(acc[a0],     Ah, Bl0[0], Bl0[1]);
                    mma16816(acc[a0 + 1], Ah, Bl0[2], Bl0[3]);
                    mma16816(acc[a0 + 2], Ah, Bl1[0], Bl1[1]);
                    mma16816(acc[a0 + 3], Ah, Bl1[2], Bl1[3]);
                }
            }
            mbar_arrive(mbF + s * 16 + 8);               // empty[s]
            if (++s == 3) { s = 0; kpar ^= 1u; }
        }

        __syncthreads();   // join with producers (Zs ready)  [A]
        // epilogue
        float* Zs = (float*)(sm + ZS_OFF);
        int g = lane >> 2, quad = lane & 3;
        int rl = mb + g;
        float zi0 = __frcp_rn(Zs[rl]);
        float zi1 = __frcp_rn(Zs[rl + 8]);
#pragma unroll
        for (int nt = 0; nt < 16; nt++) {
            int c = cb * 128 + nt * 8 + quad * 2;
            *(float2*)&out[(size_t)(r0 + rl) * FOUT + c] =
                make_float2(acc[nt][0] * zi0, acc[nt][1] * zi0);
            *(float2*)&out[(size_t)(r0 + rl + 8) * FOUT + c] =
                make_float2(acc[nt][2] * zi1, acc[nt][3] * zi1);
        }
        return;
    }
    __syncthreads();       // producers join [A]
}

// ---------------------------------------------------------------------------
extern "C" void kernel_launch(void* const* d_in, const int* in_sizes, int n_in,
                              void* d_out, int out_size) {
    const float* h   = (const float*)d_in[0];
    const int*   adj = (const int*)d_in[1];
    const float* W   = (const float*)d_in[2];
    const float* a   = (const float*)d_in[3];
    float* out = (float*)d_out;

    cudaFuncSetAttribute(k_attn, cudaFuncAttributeMaxDynamicSharedMemorySize, SM_TOT);

    k_wh<<<512, 256>>>(h, W);
    k_tr<<<256, 256>>>();
    k_s12<<<1024, 256>>>(a);
    k_attn<<<256, 256, SM_TOT>>>(adj, out);
}